// round 5
// baseline (speedup 1.0000x reference)
#include <cuda_runtime.h>
#include <cuda_fp16.h>
#include <cstdint>

// ---------------------------------------------------------------------------
// EdgeConv (mlp_layer=0, aggregate=max), restructured:
//   t      = feat @ theta_w                      [N, 64]
//   base   = t + feat @ phi_w + theta_b + phi_b  [N, 64]   (written to d_out)
//   out[v] = base[v] - min_k t[nbr[v,k]]         (per-feature min)
//
// GEMM: packed-fp32 (fma.rn.f32x2 / FFMA2) SGEMM -> 2x the scalar-FFMA rate.
// Gather: t stored as fp16 -> halves the L2-bound gather stream.
// ---------------------------------------------------------------------------

#define F_DIM 64
#define N_MAX 120000

__device__ __half g_t16[(size_t)N_MAX * F_DIM];   // fp16 t for the gather

// packed f32x2 fma: d.lo += a.lo*b.lo ; d.hi += a.hi*b.hi   (exact fp32 FMA)
#define FMA_F32X2(d, a, b) \
    asm("fma.rn.f32x2 %0, %1, %2, %0;" : "+l"(d) : "l"(a), "l"(b))

__device__ __forceinline__ float ull_lo(unsigned long long v) {
    return __uint_as_float((unsigned)(v & 0xffffffffull));
}
__device__ __forceinline__ float ull_hi(unsigned long long v) {
    return __uint_as_float((unsigned)(v >> 32));
}

// ---------------------------------------------------------------------------
// Kernel 1: fused SGEMM  C = feat @ [theta_w | phi_w]   (M=N nodes, N=128, K=64)
// BM=128 rows/block, 256 threads. Thread (tx,ty) owns rows ty*8..+7 and cols
// tx*4..+3 of BOTH theta (c<64) and phi (c>=64) halves.
// Accumulators packed along M: accT[m][j] = {C[2m][j], C[2m+1][j]} in f32x2.
// ---------------------------------------------------------------------------
#define BM 128
#define BK 16

__global__ __launch_bounds__(256)
void fused_gemm_kernel(const float* __restrict__ feat,
                       const float* __restrict__ theta_w,
                       const float* __restrict__ theta_b,
                       const float* __restrict__ phi_w,
                       const float* __restrict__ phi_b,
                       float* __restrict__ out,
                       int n)
{
    __shared__ float  sA[BK][BM + 4];    // [k][row], stride 132 (16B-aligned rows)
    __shared__ float2 sB2[BK][130];      // [k][c] duplicated {w,w}; stride 1040B

    const int tid = threadIdx.x;
    const int tx  = tid & 15;    // feature group (4 cols)
    const int ty  = tid >> 4;    // row group (8 rows)
    const int rb  = blockIdx.x * BM;

    unsigned long long accT[4][4], accP[4][4];
#pragma unroll
    for (int m = 0; m < 4; m++)
#pragma unroll
        for (int j = 0; j < 4; j++) { accT[m][j] = 0ull; accP[m][j] = 0ull; }

    for (int kk = 0; kk < F_DIM; kk += BK) {
        // --- stage A (transposed): sA[k][row] = feat[row][kk+k] ------------
        {
            const int c  = tid & 15;     // k within chunk
            const int r0 = tid >> 4;     // 0..15
#pragma unroll
            for (int p = 0; p < 8; p++) {
                int r   = r0 + p * 16;
                int row = rb + r;
                sA[c][r] = (row < n) ? feat[(size_t)row * F_DIM + kk + c] : 0.f;
            }
        }
        // --- stage B duplicated: sB2[k][c] = {w,w} --------------------------
        {
#pragma unroll
            for (int p = 0; p < 8; p++) {
                int idx = tid + p * 256;          // 0..2047
                int k   = idx >> 7;               // 0..15
                int c   = idx & 127;              // 0..127
                float v = (c < 64) ? theta_w[(kk + k) * F_DIM + c]
                                   : phi_w[(kk + k) * F_DIM + (c - 64)];
                sB2[k][c] = make_float2(v, v);
            }
        }
        __syncthreads();

#pragma unroll
        for (int k = 0; k < BK; k++) {
            // A row-pairs: {a0,a1},{a2,a3},{a4,a5},{a6,a7}
            ulonglong2 aA = *(const ulonglong2*)&sA[k][ty * 8];
            ulonglong2 aB = *(const ulonglong2*)&sA[k][ty * 8 + 4];
            unsigned long long av[4] = {aA.x, aA.y, aB.x, aB.y};
            // B duplicated pairs: theta cols tx*4..+3, phi cols 64+tx*4..+3
            ulonglong2 bt0 = *(const ulonglong2*)&sB2[k][tx * 4];
            ulonglong2 bt1 = *(const ulonglong2*)&sB2[k][tx * 4 + 2];
            ulonglong2 bp0 = *(const ulonglong2*)&sB2[k][64 + tx * 4];
            ulonglong2 bp1 = *(const ulonglong2*)&sB2[k][64 + tx * 4 + 2];
            unsigned long long bT[4] = {bt0.x, bt0.y, bt1.x, bt1.y};
            unsigned long long bP[4] = {bp0.x, bp0.y, bp1.x, bp1.y};
#pragma unroll
            for (int m = 0; m < 4; m++) {
#pragma unroll
                for (int j = 0; j < 4; j++) {
                    FMA_F32X2(accT[m][j], av[m], bT[j]);
                    FMA_F32X2(accP[m][j], av[m], bP[j]);
                }
            }
        }
        __syncthreads();
    }

    // --- epilogue: write t (fp16) and base (fp32) ---------------------------
    float bias[4];
#pragma unroll
    for (int j = 0; j < 4; j++) bias[j] = theta_b[tx * 4 + j] + phi_b[tx * 4 + j];

#pragma unroll
    for (int i = 0; i < 8; i++) {
        const int m = i >> 1;
        const int h = i & 1;
        int row = rb + ty * 8 + i;
        if (row < n) {
            float tv[4], pv[4];
#pragma unroll
            for (int j = 0; j < 4; j++) {
                tv[j] = h ? ull_hi(accT[m][j]) : ull_lo(accT[m][j]);
                pv[j] = h ? ull_hi(accP[m][j]) : ull_lo(accP[m][j]);
            }
            size_t off = (size_t)row * F_DIM + tx * 4;
            *(__half2*)&g_t16[off]     = __floats2half2_rn(tv[0], tv[1]);
            *(__half2*)&g_t16[off + 2] = __floats2half2_rn(tv[2], tv[3]);
            *(float4*)&out[off] = make_float4(tv[0] + pv[0] + bias[0],
                                              tv[1] + pv[1] + bias[1],
                                              tv[2] + pv[2] + bias[2],
                                              tv[3] + pv[3] + bias[3]);
        }
    }
}

// ---------------------------------------------------------------------------
// Kernel 2: gather-min over fp16 t. One warp per node; lane owns 2 features
// (one half2) -> warp reads 128 B per neighbor row. 32-bit offset math.
// Index dtype (int64 vs int32) detected per-warp via ballot on first 32 words.
// ---------------------------------------------------------------------------
__global__ __launch_bounds__(256)
void gather_min_kernel(const void* __restrict__ nbr_raw,
                       float* __restrict__ out,
                       int n, int K)
{
    const int lane = threadIdx.x & 31;

    unsigned int probe = ((const unsigned int*)nbr_raw)[lane];
    bool oddzero = ((lane & 1) == 0) || (probe == 0u);
    const bool is64 = (__ballot_sync(0xFFFFFFFFu, oddzero) == 0xFFFFFFFFu);

    int w = (int)((blockIdx.x * (long long)blockDim.x + threadIdx.x) >> 5);
    if (w >= n) return;

    const __half2* t2 = (const __half2*)g_t16;
    __half2 m = __float2half2_rn(65504.f);

    if (K == 16) {
        int u[16];
        if (is64) {
            const longlong2* nb = (const longlong2*)((const long long*)nbr_raw
                                                     + (size_t)w * 16);
#pragma unroll
            for (int j = 0; j < 8; j++) {
                longlong2 p = __ldg(&nb[j]);
                u[2 * j]     = (int)p.x;
                u[2 * j + 1] = (int)p.y;
            }
        } else {
            const int4* nb = (const int4*)((const int*)nbr_raw + (size_t)w * 16);
#pragma unroll
            for (int j = 0; j < 4; j++) {
                int4 p = __ldg(&nb[j]);
                u[4 * j]     = p.x;
                u[4 * j + 1] = p.y;
                u[4 * j + 2] = p.z;
                u[4 * j + 3] = p.w;
            }
        }
#pragma unroll
        for (int j = 0; j < 16; j++) {
            __half2 v = __ldg(&t2[u[j] * 32 + lane]);
            m = __hmin2(m, v);
        }
    } else {
        for (int j = 0; j < K; j++) {
            int u = is64 ? (int)((const long long*)nbr_raw)[(size_t)w * K + j]
                         : ((const int*)nbr_raw)[(size_t)w * K + j];
            __half2 v = __ldg(&t2[u * 32 + lane]);
            m = __hmin2(m, v);
        }
    }

    float2 mf = __half22float2(m);
    float2* out2 = (float2*)out;
    size_t o = (size_t)w * 32 + lane;
    float2 b = out2[o];
    b.x -= mf.x;
    b.y -= mf.y;
    out2[o] = b;
}

// ============================== launch =====================================
extern "C" void kernel_launch(void* const* d_in, const int* in_sizes, int n_in,
                              void* d_out, int out_size)
{
    const float* feat    = (const float*)d_in[0];
    const void*  nbr     = d_in[1];
    const float* theta_w = (const float*)d_in[2];
    const float* theta_b = (const float*)d_in[3];
    const float* phi_w   = (const float*)d_in[4];
    const float* phi_b   = (const float*)d_in[5];
    float* out = (float*)d_out;

    const int n = in_sizes[0] / F_DIM;     // number of nodes
    const int K = in_sizes[1] / n;         // neighbors per node (=16)

    int g1 = (n + BM - 1) / BM;
    fused_gemm_kernel<<<g1, 256>>>(feat, theta_w, theta_b, phi_w, phi_b, out, n);

    long long total_threads = (long long)n * 32;
    int g2 = (int)((total_threads + 255) / 256);
    gather_min_kernel<<<g2, 256>>>(nbr, out, n, K);
}

// round 6
// speedup vs baseline: 1.4548x; 1.4548x over previous
#include <cuda_runtime.h>
#include <cuda_fp16.h>
#include <cstdint>

// ---------------------------------------------------------------------------
// EdgeConv (mlp_layer=0, aggregate=max), restructured:
//   t      = feat @ theta_w                      [N, 64]
//   base   = t + feat @ phi_w + theta_b + phi_b  [N, 64]   (written to d_out)
//   out[v] = base[v] - min_k t[nbr[v,k]]         (per-feature min)
//
// GEMM: legacy tensor cores (mma.sync m16n8k16 fp16, hi/lo split, 3 passes ->
// ~fp32 accuracy), lean tiling: 64-row CTA, 32 acc regs/thread, single stage.
// Gather: t stored as fp16 -> halves the L2-bound gather stream.
// ---------------------------------------------------------------------------

#define F_DIM 64
#define N_MAX 120000

__device__ __half g_t16[(size_t)N_MAX * F_DIM];   // fp16 t for the gather

// ============================= PTX helpers =================================
__device__ __forceinline__ uint32_t smem_u32(const void* p) {
    uint32_t a;
    asm("{ .reg .u64 tmp; cvta.to.shared.u64 tmp, %1; cvt.u32.u64 %0, tmp; }"
        : "=r"(a) : "l"(p));
    return a;
}

__device__ __forceinline__ void ldsm_x4(uint32_t* r, uint32_t addr) {
    asm volatile("ldmatrix.sync.aligned.m8n8.x4.shared.b16 {%0,%1,%2,%3}, [%4];"
                 : "=r"(r[0]), "=r"(r[1]), "=r"(r[2]), "=r"(r[3]) : "r"(addr));
}

__device__ __forceinline__ void mma16816(float* c, const uint32_t* a,
                                         const uint32_t* b) {
    asm volatile(
        "mma.sync.aligned.m16n8k16.row.col.f32.f16.f16.f32 "
        "{%0,%1,%2,%3}, {%4,%5,%6,%7}, {%8,%9}, {%0,%1,%2,%3};"
        : "+f"(c[0]), "+f"(c[1]), "+f"(c[2]), "+f"(c[3])
        : "r"(a[0]), "r"(a[1]), "r"(a[2]), "r"(a[3]), "r"(b[0]), "r"(b[1]));
}

// fp16 hi/lo split of two floats -> packed hi word + lo word
__device__ __forceinline__ uint32_t pack_hilo(float x, float y,
                                              uint32_t& lo_out) {
    __half hx = __float2half_rn(x);
    __half hy = __float2half_rn(y);
    __half lx = __float2half_rn(x - __half2float(hx));
    __half ly = __float2half_rn(y - __half2float(hy));
    lo_out = (uint32_t)__half_as_ushort(lx) |
             ((uint32_t)__half_as_ushort(ly) << 16);
    return (uint32_t)__half_as_ushort(hx) |
           ((uint32_t)__half_as_ushort(hy) << 16);
}

// SMEM layout (dynamic, bytes). Rows padded to 72 fp16 = 144 B (ldmatrix
// conflict-free: 8 rows x 144 B hit 8 distinct 16B bank groups).
#define SM_AH 0
#define SM_AL 9216
#define SM_BH 18432
#define SM_BL 36864
#define SM_BYTES 55296

// ============================ GEMM kernel ==================================
// CTA: 64 rows x full N=128 ([theta|phi]). 8 warps: wm=(wid&1)*32,
// wn=(wid>>1)*16. Warp owns theta cols wn..wn+15 and phi cols 64+wn..64+wn+15
// -> t and base combine in registers.
__global__ __launch_bounds__(256)
void gemm_mma_kernel(const float* __restrict__ feat,
                     const float* __restrict__ theta_w,
                     const float* __restrict__ theta_b,
                     const float* __restrict__ phi_w,
                     const float* __restrict__ phi_b,
                     float* __restrict__ out,
                     int n)
{
    extern __shared__ char sm[];
    const uint32_t sbase = smem_u32(sm);
    const int tid = threadIdx.x;
    const int rb  = blockIdx.x * 64;

    // ---- stage A: feat[rb..rb+63][0..63] -> fp16 hi/lo (coalesced f4) -----
#pragma unroll
    for (int p = 0; p < 4; p++) {
        int idx = tid + p * 256;         // 0..1023
        int c4  = idx & 15;              // float4 column group
        int row = idx >> 4;              // 0..63
        float4 f = make_float4(0.f, 0.f, 0.f, 0.f);
        int gr = rb + row;
        if (gr < n) f = *(const float4*)&feat[(size_t)gr * F_DIM + c4 * 4];
        uint32_t l0, l1;
        uint32_t h0 = pack_hilo(f.x, f.y, l0);
        uint32_t h1 = pack_hilo(f.z, f.w, l1);
        uint32_t off = row * 144 + c4 * 8;
        *(uint2*)(sm + SM_AH + off) = make_uint2(h0, h1);
        *(uint2*)(sm + SM_AL + off) = make_uint2(l0, l1);
    }

    // ---- stage B: B[nrow][k] = w[k][nrow]; nrow<64 theta, >=64 phi --------
#pragma unroll
    for (int p = 0; p < 8; p++) {
        int idx  = tid + p * 256;        // 0..2047
        int c4   = idx & 15;             // k group of 4
        int nrow = idx >> 4;             // 0..127
        const float* w = (nrow < 64) ? theta_w : phi_w;
        int nc = nrow & 63;
        float v0 = w[(c4 * 4 + 0) * F_DIM + nc];
        float v1 = w[(c4 * 4 + 1) * F_DIM + nc];
        float v2 = w[(c4 * 4 + 2) * F_DIM + nc];
        float v3 = w[(c4 * 4 + 3) * F_DIM + nc];
        uint32_t l0, l1;
        uint32_t h0 = pack_hilo(v0, v1, l0);
        uint32_t h1 = pack_hilo(v2, v3, l1);
        uint32_t off = nrow * 144 + c4 * 8;
        *(uint2*)(sm + SM_BH + off) = make_uint2(h0, h1);
        *(uint2*)(sm + SM_BL + off) = make_uint2(l0, l1);
    }
    __syncthreads();

    const int wid  = tid >> 5;
    const int lane = tid & 31;
    const int wm   = (wid & 1) * 32;
    const int wn   = (wid >> 1) * 16;
    const int li   = lane & 7;
    const int lg   = lane >> 3;

    float accT[2][2][4], accP[2][2][4];
#pragma unroll
    for (int mt = 0; mt < 2; mt++)
#pragma unroll
        for (int nt = 0; nt < 2; nt++)
#pragma unroll
            for (int j = 0; j < 4; j++) {
                accT[mt][nt][j] = 0.f;
                accP[mt][nt][j] = 0.f;
            }

#pragma unroll
    for (int p = 0; p < 3; p++) {
        const uint32_t aoff = (p == 1) ? SM_AL : SM_AH;
        const uint32_t boff = (p == 2) ? SM_BL : SM_BH;
#pragma unroll
        for (int ks = 0; ks < 4; ks++) {
            const int k0 = ks * 16;
            uint32_t a[2][4];
#pragma unroll
            for (int mt = 0; mt < 2; mt++) {
                int row = wm + mt * 16 + li + (lg & 1) * 8;
                int col = k0 + (lg >> 1) * 8;
                ldsm_x4(a[mt], sbase + aoff + row * 144 + col * 2);
            }
            uint32_t bT[2][2], bP[2][2];
            {
                int row = wn + li + (lg >> 1) * 8;
                int col = k0 + (lg & 1) * 8;
                uint32_t r[4];
                ldsm_x4(r, sbase + boff + row * 144 + col * 2);
                bT[0][0] = r[0]; bT[0][1] = r[1];
                bT[1][0] = r[2]; bT[1][1] = r[3];
                ldsm_x4(r, sbase + boff + (64 + row) * 144 + col * 2);
                bP[0][0] = r[0]; bP[0][1] = r[1];
                bP[1][0] = r[2]; bP[1][1] = r[3];
            }
#pragma unroll
            for (int mt = 0; mt < 2; mt++)
#pragma unroll
                for (int nt = 0; nt < 2; nt++) {
                    mma16816(accT[mt][nt], a[mt], bT[nt]);
                    mma16816(accP[mt][nt], a[mt], bP[nt]);
                }
        }
    }

    // ---- epilogue: direct register combine + store -------------------------
#pragma unroll
    for (int mt = 0; mt < 2; mt++) {
        int r0 = rb + wm + mt * 16 + (lane >> 2);
#pragma unroll
        for (int nt = 0; nt < 2; nt++) {
            int col = wn + nt * 8 + 2 * (lane & 3);
            float b0 = theta_b[col]     + phi_b[col];
            float b1 = theta_b[col + 1] + phi_b[col + 1];
            if (r0 < n) {
                size_t o = (size_t)r0 * F_DIM + col;
                float t0 = accT[mt][nt][0], t1 = accT[mt][nt][1];
                *(__half2*)&g_t16[o] = __floats2half2_rn(t0, t1);
                *(float2*)&out[o] = make_float2(t0 + accP[mt][nt][0] + b0,
                                                t1 + accP[mt][nt][1] + b1);
            }
            int r1 = r0 + 8;
            if (r1 < n) {
                size_t o = (size_t)r1 * F_DIM + col;
                float t2 = accT[mt][nt][2], t3 = accT[mt][nt][3];
                *(__half2*)&g_t16[o] = __floats2half2_rn(t2, t3);
                *(float2*)&out[o] = make_float2(t2 + accP[mt][nt][2] + b0,
                                                t3 + accP[mt][nt][3] + b1);
            }
        }
    }
}

// ---------------------------------------------------------------------------
// Kernel 2: gather-min over fp16 t. One warp per node; lane owns 2 features
// (one half2) -> warp reads 128 B per neighbor row. 32-bit offset math.
// Index dtype (int64 vs int32) detected per-warp via ballot on first 32 words.
// ---------------------------------------------------------------------------
__global__ __launch_bounds__(256)
void gather_min_kernel(const void* __restrict__ nbr_raw,
                       float* __restrict__ out,
                       int n, int K)
{
    const int lane = threadIdx.x & 31;

    unsigned int probe = ((const unsigned int*)nbr_raw)[lane];
    bool oddzero = ((lane & 1) == 0) || (probe == 0u);
    const bool is64 = (__ballot_sync(0xFFFFFFFFu, oddzero) == 0xFFFFFFFFu);

    int w = (int)((blockIdx.x * (long long)blockDim.x + threadIdx.x) >> 5);
    if (w >= n) return;

    const __half2* t2 = (const __half2*)g_t16;
    __half2 m = __float2half2_rn(65504.f);

    if (K == 16) {
        int u[16];
        if (is64) {
            const longlong2* nb = (const longlong2*)((const long long*)nbr_raw
                                                     + (size_t)w * 16);
#pragma unroll
            for (int j = 0; j < 8; j++) {
                longlong2 p = __ldg(&nb[j]);
                u[2 * j]     = (int)p.x;
                u[2 * j + 1] = (int)p.y;
            }
        } else {
            const int4* nb = (const int4*)((const int*)nbr_raw + (size_t)w * 16);
#pragma unroll
            for (int j = 0; j < 4; j++) {
                int4 p = __ldg(&nb[j]);
                u[4 * j]     = p.x;
                u[4 * j + 1] = p.y;
                u[4 * j + 2] = p.z;
                u[4 * j + 3] = p.w;
            }
        }
#pragma unroll
        for (int j = 0; j < 16; j++) {
            __half2 v = __ldg(&t2[u[j] * 32 + lane]);
            m = __hmin2(m, v);
        }
    } else {
        for (int j = 0; j < K; j++) {
            int u = is64 ? (int)((const long long*)nbr_raw)[(size_t)w * K + j]
                         : ((const int*)nbr_raw)[(size_t)w * K + j];
            __half2 v = __ldg(&t2[u * 32 + lane]);
            m = __hmin2(m, v);
        }
    }

    float2 mf = __half22float2(m);
    float2* out2 = (float2*)out;
    size_t o = (size_t)w * 32 + lane;
    float2 b = out2[o];
    b.x -= mf.x;
    b.y -= mf.y;
    out2[o] = b;
}

// ============================== launch =====================================
extern "C" void kernel_launch(void* const* d_in, const int* in_sizes, int n_in,
                              void* d_out, int out_size)
{
    const float* feat    = (const float*)d_in[0];
    const void*  nbr     = d_in[1];
    const float* theta_w = (const float*)d_in[2];
    const float* theta_b = (const float*)d_in[3];
    const float* phi_w   = (const float*)d_in[4];
    const float* phi_b   = (const float*)d_in[5];
    float* out = (float*)d_out;

    const int n = in_sizes[0] / F_DIM;     // number of nodes
    const int K = in_sizes[1] / n;         // neighbors per node (=16)

    static int smem_set = 0;
    if (!smem_set) {
        cudaFuncSetAttribute(gemm_mma_kernel,
                             cudaFuncAttributeMaxDynamicSharedMemorySize,
                             SM_BYTES);
        smem_set = 1;
    }

    int g1 = (n + 63) / 64;
    gemm_mma_kernel<<<g1, 256, SM_BYTES>>>(feat, theta_w, theta_b, phi_w,
                                           phi_b, out, n);

    long long total_threads = (long long)n * 32;
    int g2 = (int)((total_threads + 255) / 256);
    gather_min_kernel<<<g2, 256>>>(nbr, out, n, K);
}